// round 3
// baseline (speedup 1.0000x reference)
#include <cuda_runtime.h>
#include <cmath>
#include <cstdint>

#define N_NODES 20000
#define N_EDGES 320000
#define CDIM    128
#define HEADS   8

// ---------------- scratch (device globals; no allocation allowed) ----------------
__device__ __align__(16) float g_sln[N_NODES * CDIM];
__device__ __align__(16) float g_q  [N_NODES * CDIM];
__device__ __align__(16) float g_k  [N_NODES * CDIM];
__device__ __align__(16) float g_h1 [N_NODES * CDIM];
__device__ __align__(16) float g_h2 [N_NODES * CDIM];
__device__ __align__(16) float g_x3 [N_NODES * 3 * CDIM];
__device__ __align__(16) float g_val[N_NODES * 3 * CDIM];
__device__ __align__(16) float g_rproj[(size_t)N_EDGES * 3 * CDIM];
__device__ __align__(16) float g_alpha[N_EDGES * HEADS];
__device__ unsigned g_m[N_NODES * HEADS];
__device__ float    g_z[N_NODES * HEADS];

__device__ __forceinline__ unsigned enc_f(float x) {
    unsigned u = __float_as_uint(x);
    return (u & 0x80000000u) ? ~u : (u | 0x80000000u);
}
__device__ __forceinline__ float dec_f(unsigned u) {
    u = (u & 0x80000000u) ? (u & 0x7fffffffu) : ~u;
    return __uint_as_float(u);
}

__device__ __forceinline__ float to_tf32(float x) {
    uint32_t u;
    asm("cvt.rna.tf32.f32 %0, %1;" : "=r"(u) : "f"(x));
    return __uint_as_float(u);
}

__device__ __forceinline__ void mma_tf32(float* c, const uint32_t* a, const uint32_t* b) {
    asm volatile(
        "mma.sync.aligned.m16n8k8.row.col.f32.tf32.tf32.f32 "
        "{%0,%1,%2,%3}, {%4,%5,%6,%7}, {%8,%9}, {%0,%1,%2,%3};"
        : "+f"(c[0]), "+f"(c[1]), "+f"(c[2]), "+f"(c[3])
        : "r"(a[0]), "r"(a[1]), "r"(a[2]), "r"(a[3]), "r"(b[0]), "r"(b[1]));
}

// ---------------- init accumulators ----------------
__global__ void init_kernel() {
    int i = blockIdx.x * blockDim.x + threadIdx.x;
    if (i < N_NODES * HEADS) {
        g_m[i] = 0x007FFFFFu;  // enc(-inf)
        g_z[i] = 0.0f;
    }
}

// ---------------- layernorm ----------------
__global__ void ln_kernel(const float* __restrict__ s, const float* __restrict__ g,
                          const float* __restrict__ b, float* __restrict__ out_s) {
    int n = blockIdx.x;
    int c = threadIdx.x;
    float x = s[n * CDIM + c];
    __shared__ float red[4];
    int lane = c & 31, w = c >> 5;
    float sum = x;
    #pragma unroll
    for (int o = 16; o > 0; o >>= 1) sum += __shfl_xor_sync(0xffffffffu, sum, o);
    if (lane == 0) red[w] = sum;
    __syncthreads();
    float mean = (red[0] + red[1] + red[2] + red[3]) * (1.0f / 128.0f);
    float d = x - mean;
    float sq = d * d;
    #pragma unroll
    for (int o = 16; o > 0; o >>= 1) sq += __shfl_xor_sync(0xffffffffu, sq, o);
    __syncthreads();
    if (lane == 0) red[w] = sq;
    __syncthreads();
    float var = (red[0] + red[1] + red[2] + red[3]) * (1.0f / 128.0f);
    float y = d * rsqrtf(var + 1e-5f) * g[c] + b[c];
    g_sln[n * CDIM + c] = y;
    out_s[n * CDIM + c] = y;
}

// ======================= double-buffered tf32 GEMM core =======================
// Block tile 128x128, K=128 in 8 chunks of 16, 8 warps, warp tile 32x64.

struct Task {
    const float* A; const float* Bw; const float* bias; float* C;
    int M; int Nc; int act;
};
struct Task4 { Task t[4]; };

#define GEMM_SMEM_DECL \
    __shared__ float As[2][128][20]; \
    __shared__ float Bs[2][16][136];

__device__ __forceinline__ void ldg_chunk(const float* __restrict__ A,
                                          const float* __restrict__ B,
                                          int bm, int M, int Nc, int bn, int k0, int tid,
                                          float4& a0, float4& a1, float4& b0, float4& b1) {
    int row = tid >> 2, kq = (tid & 3) << 2;
    a0 = (bm + row < M) ? *(const float4*)(A + (size_t)(bm + row) * 128 + k0 + kq)
                        : make_float4(0.f, 0.f, 0.f, 0.f);
    int row1 = row + 64;
    a1 = (bm + row1 < M) ? *(const float4*)(A + (size_t)(bm + row1) * 128 + k0 + kq)
                         : make_float4(0.f, 0.f, 0.f, 0.f);
    int kr = tid >> 5, nq = (tid & 31) << 2;
    b0 = *(const float4*)(B + (size_t)(k0 + kr) * Nc + bn + nq);
    b1 = *(const float4*)(B + (size_t)(k0 + kr + 8) * Nc + bn + nq);
}

#define STS_CHUNK(buf, a0, a1, b0, b1) do {                                   \
    int row = tid >> 2, kq = (tid & 3) << 2;                                  \
    As[buf][row][kq+0] = to_tf32(a0.x); As[buf][row][kq+1] = to_tf32(a0.y);   \
    As[buf][row][kq+2] = to_tf32(a0.z); As[buf][row][kq+3] = to_tf32(a0.w);   \
    As[buf][row+64][kq+0] = to_tf32(a1.x); As[buf][row+64][kq+1] = to_tf32(a1.y); \
    As[buf][row+64][kq+2] = to_tf32(a1.z); As[buf][row+64][kq+3] = to_tf32(a1.w); \
    int kr = tid >> 5, nq = (tid & 31) << 2;                                  \
    Bs[buf][kr][nq+0] = to_tf32(b0.x); Bs[buf][kr][nq+1] = to_tf32(b0.y);     \
    Bs[buf][kr][nq+2] = to_tf32(b0.z); Bs[buf][kr][nq+3] = to_tf32(b0.w);     \
    Bs[buf][kr+8][nq+0] = to_tf32(b1.x); Bs[buf][kr+8][nq+1] = to_tf32(b1.y); \
    Bs[buf][kr+8][nq+2] = to_tf32(b1.z); Bs[buf][kr+8][nq+3] = to_tf32(b1.w); \
} while (0)

#define MMA_CHUNK(buf) do {                                                   \
    _Pragma("unroll")                                                         \
    for (int kk = 0; kk < 16; kk += 8) {                                      \
        uint32_t bf[8][2];                                                    \
        _Pragma("unroll")                                                     \
        for (int ni = 0; ni < 8; ni++) {                                      \
            bf[ni][0] = __float_as_uint(Bs[buf][kk + tig    ][wn + ni * 8 + gid]); \
            bf[ni][1] = __float_as_uint(Bs[buf][kk + tig + 4][wn + ni * 8 + gid]); \
        }                                                                     \
        _Pragma("unroll")                                                     \
        for (int mi = 0; mi < 2; mi++) {                                      \
            uint32_t af[4];                                                   \
            af[0] = __float_as_uint(As[buf][wm + mi * 16 + gid    ][kk + tig    ]); \
            af[1] = __float_as_uint(As[buf][wm + mi * 16 + gid + 8][kk + tig    ]); \
            af[2] = __float_as_uint(As[buf][wm + mi * 16 + gid    ][kk + tig + 4]); \
            af[3] = __float_as_uint(As[buf][wm + mi * 16 + gid + 8][kk + tig + 4]); \
            _Pragma("unroll")                                                 \
            for (int ni = 0; ni < 8; ni++) mma_tf32(acc[mi][ni], af, bf[ni]); \
        }                                                                     \
    }                                                                         \
} while (0)

#define GEMM_MAINLOOP(Aptr, Bptr, Mv, Ncv)                                    \
    float acc[2][8][4];                                                       \
    _Pragma("unroll")                                                         \
    for (int mi = 0; mi < 2; mi++)                                            \
        _Pragma("unroll")                                                     \
        for (int ni = 0; ni < 8; ni++)                                        \
            _Pragma("unroll")                                                 \
            for (int t = 0; t < 4; t++) acc[mi][ni][t] = 0.0f;                \
    {                                                                         \
        float4 a0, a1, b0, b1;                                                \
        ldg_chunk(Aptr, Bptr, bm, Mv, Ncv, bn, 0, tid, a0, a1, b0, b1);       \
        STS_CHUNK(0, a0, a1, b0, b1);                                         \
        __syncthreads();                                                      \
        _Pragma("unroll")                                                     \
        for (int c = 0; c < 8; c++) {                                         \
            int cur = c & 1;                                                  \
            if (c < 7) ldg_chunk(Aptr, Bptr, bm, Mv, Ncv, bn, (c + 1) * 16, tid, a0, a1, b0, b1); \
            MMA_CHUNK(cur);                                                   \
            if (c < 7) STS_CHUNK(cur ^ 1, a0, a1, b0, b1);                    \
            __syncthreads();                                                  \
        }                                                                     \
    }

// ---------------- multi-task GEMM: C = act(A @ B + bias) ----------------
__global__ void __launch_bounds__(256)
gemm_multi(Task4 ts) {
    GEMM_SMEM_DECL
    const Task tk = ts.t[blockIdx.z];
    const int bm = blockIdx.x * 128;
    const int bn = blockIdx.y * 128;
    const int tid = threadIdx.x;
    const int warp = tid >> 5, lane = tid & 31;
    const int gid = lane >> 2, tig = lane & 3;
    const int wm = (warp & 3) * 32;
    const int wn = (warp >> 2) * 64;
    const int M = tk.M, Nc = tk.Nc;

    GEMM_MAINLOOP(tk.A, tk.Bw, M, Nc)

    #pragma unroll
    for (int mi = 0; mi < 2; mi++) {
        int r0 = bm + wm + mi * 16 + gid;
        int r1 = r0 + 8;
        #pragma unroll
        for (int ni = 0; ni < 8; ni++) {
            int col = bn + wn + ni * 8 + tig * 2;
            float bb0 = tk.bias[col], bb1 = tk.bias[col + 1];
            float v0 = acc[mi][ni][0] + bb0;
            float v1 = acc[mi][ni][1] + bb1;
            float v2 = acc[mi][ni][2] + bb0;
            float v3 = acc[mi][ni][3] + bb1;
            if (tk.act) {
                v0 = v0 / (1.0f + expf(-v0));
                v1 = v1 / (1.0f + expf(-v1));
                v2 = v2 / (1.0f + expf(-v2));
                v3 = v3 / (1.0f + expf(-v3));
            }
            if (r0 < M) { float2 o = make_float2(v0, v1); *(float2*)(tk.C + (size_t)r0 * Nc + col) = o; }
            if (r1 < M) { float2 o = make_float2(v2, v3); *(float2*)(tk.C + (size_t)r1 * Nc + col) = o; }
        }
    }
}

// ---------------- Wre GEMM with fused alpha + segment-max epilogue ----------------
// r_attn = silu(rij @ Wre + bre) never hits DRAM; alpha[e,h] computed in-register.
__global__ void __launch_bounds__(256)
gemm_wre_alpha(const float* __restrict__ A, const float* __restrict__ Bw,
               const float* __restrict__ bias, const int* __restrict__ ei,
               const float* __restrict__ q, const float* __restrict__ k) {
    GEMM_SMEM_DECL
    const int bm = blockIdx.x * 128;
    const int bn = 0;
    const int tid = threadIdx.x;
    const int warp = tid >> 5, lane = tid & 31;
    const int gid = lane >> 2, tig = lane & 3;
    const int wm = (warp & 3) * 32;
    const int wn = (warp >> 2) * 64;

    GEMM_MAINLOOP(A, Bw, N_EDGES, 128)

    float apart[2][2][4];
    #pragma unroll
    for (int mi = 0; mi < 2; mi++)
        #pragma unroll
        for (int rh = 0; rh < 2; rh++)
            #pragma unroll
            for (int hh = 0; hh < 4; hh++) apart[mi][rh][hh] = 0.0f;

    #pragma unroll
    for (int mi = 0; mi < 2; mi++) {
        int r0 = bm + wm + mi * 16 + gid;
        int r1 = r0 + 8;
        int s0 = ei[r0], d0 = ei[N_EDGES + r0];
        int s1 = ei[r1], d1 = ei[N_EDGES + r1];
        #pragma unroll
        for (int ni = 0; ni < 8; ni++) {
            int col = wn + ni * 8 + tig * 2;
            float bb0 = bias[col], bb1 = bias[col + 1];
            float v0 = acc[mi][ni][0] + bb0; v0 = v0 / (1.0f + expf(-v0));
            float v1 = acc[mi][ni][1] + bb1; v1 = v1 / (1.0f + expf(-v1));
            float v2 = acc[mi][ni][2] + bb0; v2 = v2 / (1.0f + expf(-v2));
            float v3 = acc[mi][ni][3] + bb1; v3 = v3 / (1.0f + expf(-v3));
            float2 q0 = *(const float2*)(q + (size_t)d0 * 128 + col);
            float2 k0 = *(const float2*)(k + (size_t)s0 * 128 + col);
            float2 q1 = *(const float2*)(q + (size_t)d1 * 128 + col);
            float2 k1 = *(const float2*)(k + (size_t)s1 * 128 + col);
            int hh = ni >> 1;
            apart[mi][0][hh] += v0 * q0.x * k0.x + v1 * q0.y * k0.y;
            apart[mi][1][hh] += v2 * q1.x * k1.x + v3 * q1.y * k1.y;
        }
    }

    #pragma unroll
    for (int mi = 0; mi < 2; mi++)
        #pragma unroll
        for (int rh = 0; rh < 2; rh++)
            #pragma unroll
            for (int hh = 0; hh < 4; hh++) {
                float v = apart[mi][rh][hh];
                v += __shfl_xor_sync(0xffffffffu, v, 1);
                v += __shfl_xor_sync(0xffffffffu, v, 2);
                if (tig == 0) {
                    int e = bm + wm + mi * 16 + gid + rh * 8;
                    int h = (wn >> 4) + hh;
                    int dd = ei[N_EDGES + e];
                    g_alpha[(size_t)e * HEADS + h] = v;
                    atomicMax(&g_m[dd * HEADS + h], enc_f(v));
                }
            }
}

// ---------------- e = exp(alpha - m[dst]); z[dst] += e ----------------
__global__ void exp_kernel(const int* __restrict__ ei) {
    int i = blockIdx.x * blockDim.x + threadIdx.x;
    if (i >= N_EDGES * HEADS) return;
    int e = i >> 3;
    int h = i & 7;
    int dst = ei[N_EDGES + e];
    float m = dec_f(g_m[dst * HEADS + h]);
    if (!isfinite(m)) m = 0.0f;
    float ex = expf(g_alpha[i] - m);
    g_alpha[i] = ex;
    atomicAdd(&g_z[dst * HEADS + h], ex);
}

// ---------------- per-edge message + scatter-add ----------------
__global__ void msg_kernel(const int* __restrict__ ei, const float* __restrict__ dir,
                           const float* __restrict__ dij, const float* __restrict__ v,
                           float* __restrict__ out_s, float* __restrict__ out_v) {
    int e = blockIdx.x;
    int c = threadIdx.x;
    int src = ei[e];
    int dst = ei[N_EDGES + e];
    float d = dij[e];
    float cc = (d < 5.0f) ? 0.5f * (cosf(d * 0.62831853071795865f) + 1.0f) : 0.0f;

    const float* rp  = g_rproj + (size_t)e * 384;
    const float* x3s = g_x3 + (size_t)src * 384;
    const float* vs  = g_val + (size_t)src * 384;
    const float* al  = g_alpha + (size_t)e * HEADS;

    float msg[3];
    #pragma unroll
    for (int t = 0; t < 3; t++) {
        int j = c + t * 128;
        int h = j / 48;
        float a = al[h] / (g_z[dst * HEADS + h] + 1e-16f);
        msg[t] = rp[j] * x3s[j] * cc + a * vs[j];
    }

    atomicAdd(&out_s[(size_t)dst * 128 + c], msg[0]);
    float d0 = dir[e * 3 + 0], d1 = dir[e * 3 + 1], d2 = dir[e * 3 + 2];
    const float* vsrc = v + (size_t)src * 384;
    atomicAdd(&out_v[(size_t)dst * 384 + c],        d0 * msg[1] + msg[2] * vsrc[c]);
    atomicAdd(&out_v[(size_t)dst * 384 + 128 + c],  d1 * msg[1] + msg[2] * vsrc[128 + c]);
    atomicAdd(&out_v[(size_t)dst * 384 + 256 + c],  d2 * msg[1] + msg[2] * vsrc[256 + c]);
}

// ---------------- launch ----------------
extern "C" void kernel_launch(void* const* d_in, const int* in_sizes, int n_in,
                              void* d_out, int out_size) {
    const float* s   = (const float*)d_in[0];
    const float* v   = (const float*)d_in[1];
    const float* dir = (const float*)d_in[2];
    const float* dij = (const float*)d_in[3];
    const float* rij = (const float*)d_in[4];
    const int*   ei  = (const int*)d_in[5];
    const float* lng = (const float*)d_in[6];
    const float* lnb = (const float*)d_in[7];
    const float* Wq  = (const float*)d_in[8];  const float* bq  = (const float*)d_in[9];
    const float* Wk  = (const float*)d_in[10]; const float* bk  = (const float*)d_in[11];
    const float* Wg1 = (const float*)d_in[12]; const float* bg1 = (const float*)d_in[13];
    const float* Wg2 = (const float*)d_in[14]; const float* bg2 = (const float*)d_in[15];
    const float* Wv1 = (const float*)d_in[16]; const float* bv1 = (const float*)d_in[17];
    const float* Wv2 = (const float*)d_in[18]; const float* bv2 = (const float*)d_in[19];
    const float* Wre = (const float*)d_in[20]; const float* bre = (const float*)d_in[21];
    const float* Wra = (const float*)d_in[22]; const float* bra = (const float*)d_in[23];

    float* out   = (float*)d_out;
    float* out_s = out;
    float* out_v = out + (size_t)N_NODES * CDIM;
    float* out_r = out_v + (size_t)N_NODES * 3 * CDIM;

    float *p_sln, *p_q, *p_k, *p_h1, *p_h2, *p_x3, *p_val, *p_rproj;
    cudaGetSymbolAddress((void**)&p_sln,   g_sln);
    cudaGetSymbolAddress((void**)&p_q,     g_q);
    cudaGetSymbolAddress((void**)&p_k,     g_k);
    cudaGetSymbolAddress((void**)&p_h1,    g_h1);
    cudaGetSymbolAddress((void**)&p_h2,    g_h2);
    cudaGetSymbolAddress((void**)&p_x3,    g_x3);
    cudaGetSymbolAddress((void**)&p_val,   g_val);
    cudaGetSymbolAddress((void**)&p_rproj, g_rproj);

    cudaMemcpyAsync(out_v, v,   sizeof(float) * (size_t)N_NODES * 3 * CDIM,
                    cudaMemcpyDeviceToDevice, 0);
    cudaMemcpyAsync(out_r, rij, sizeof(float) * (size_t)N_EDGES * CDIM,
                    cudaMemcpyDeviceToDevice, 0);

    init_kernel<<<(N_NODES * HEADS + 255) / 256, 256>>>();
    ln_kernel<<<N_NODES, 128>>>(s, lng, lnb, out_s);

    const int mb_n = (N_NODES + 127) / 128;   // 157
    const int mb_e = N_EDGES / 128;           // 2500

    // 4 node GEMMs (C->C), one launch
    Task4 tA;
    tA.t[0] = { p_sln, Wq,  bq,  p_q,  N_NODES, 128, 0 };
    tA.t[1] = { p_sln, Wk,  bk,  p_k,  N_NODES, 128, 0 };
    tA.t[2] = { p_sln, Wg1, bg1, p_h1, N_NODES, 128, 1 };
    tA.t[3] = { p_sln, Wv1, bv1, p_h2, N_NODES, 128, 1 };
    gemm_multi<<<dim3(mb_n, 1, 4), 256>>>(tA);

    // 2 node GEMMs (C->3C), one launch
    Task4 tB;
    tB.t[0] = { p_h1, Wg2, bg2, p_x3,  N_NODES, 384, 0 };
    tB.t[1] = { p_h2, Wv2, bv2, p_val, N_NODES, 384, 0 };
    tB.t[2] = tB.t[0]; tB.t[3] = tB.t[0];
    gemm_multi<<<dim3(mb_n, 3, 2), 256>>>(tB);

    // edge GEMM rij @ Wra (E x 384)
    Task4 tC;
    tC.t[0] = { rij, Wra, bra, p_rproj, N_EDGES, 384, 0 };
    tC.t[1] = tC.t[0]; tC.t[2] = tC.t[0]; tC.t[3] = tC.t[0];
    gemm_multi<<<dim3(mb_e, 3, 1), 256>>>(tC);

    // edge GEMM rij @ Wre with fused silu + alpha + segment max (needs q,k)
    gemm_wre_alpha<<<mb_e, 256>>>(rij, Wre, bre, ei, p_q, p_k);

    exp_kernel<<<(N_EDGES * HEADS + 255) / 256, 256>>>(ei);
    msg_kernel<<<N_EDGES, 128>>>(ei, dir, dij, v, out_s, out_v);
}

// round 4
// speedup vs baseline: 1.0430x; 1.0430x over previous
#include <cuda_runtime.h>
#include <cmath>
#include <cstdint>

#define N_NODES 20000
#define N_EDGES 320000
#define CDIM    128
#define HEADS   8

// ---------------- scratch (device globals; no allocation allowed) ----------------
__device__ __align__(16) float g_sln[N_NODES * CDIM];
__device__ __align__(16) float g_q  [N_NODES * CDIM];
__device__ __align__(16) float g_k  [N_NODES * CDIM];
__device__ __align__(16) float g_h1 [N_NODES * CDIM];
__device__ __align__(16) float g_h2 [N_NODES * CDIM];
__device__ __align__(16) float g_x3 [N_NODES * 3 * CDIM];
__device__ __align__(16) float g_val[N_NODES * 3 * CDIM];
__device__ __align__(16) float g_rattn[(size_t)N_EDGES * CDIM];
__device__ __align__(16) float g_rproj[(size_t)N_EDGES * 3 * CDIM];
__device__ __align__(16) float g_alpha[N_EDGES * HEADS];
__device__ unsigned g_m[N_NODES * HEADS];
__device__ float    g_z[N_NODES * HEADS];

__device__ __forceinline__ unsigned enc_f(float x) {
    unsigned u = __float_as_uint(x);
    return (u & 0x80000000u) ? ~u : (u | 0x80000000u);
}
__device__ __forceinline__ float dec_f(unsigned u) {
    u = (u & 0x80000000u) ? (u & 0x7fffffffu) : ~u;
    return __uint_as_float(u);
}

__device__ __forceinline__ float to_tf32(float x) {
    uint32_t u;
    asm("cvt.rna.tf32.f32 %0, %1;" : "=r"(u) : "f"(x));
    return __uint_as_float(u);
}

__device__ __forceinline__ void mma_tf32(float* c, const uint32_t* a, const uint32_t* b) {
    asm volatile(
        "mma.sync.aligned.m16n8k8.row.col.f32.tf32.tf32.f32 "
        "{%0,%1,%2,%3}, {%4,%5,%6,%7}, {%8,%9}, {%0,%1,%2,%3};"
        : "+f"(c[0]), "+f"(c[1]), "+f"(c[2]), "+f"(c[3])
        : "r"(a[0]), "r"(a[1]), "r"(a[2]), "r"(a[3]), "r"(b[0]), "r"(b[1]));
}

// ---------------- init accumulators ----------------
__global__ void init_kernel() {
    int i = blockIdx.x * blockDim.x + threadIdx.x;
    if (i < N_NODES * HEADS) {
        g_m[i] = 0x007FFFFFu;  // enc(-inf)
        g_z[i] = 0.0f;
    }
}

// ---------------- layernorm ----------------
__global__ void ln_kernel(const float* __restrict__ s, const float* __restrict__ g,
                          const float* __restrict__ b, float* __restrict__ out_s) {
    int n = blockIdx.x;
    int c = threadIdx.x;
    float x = s[n * CDIM + c];
    __shared__ float red[4];
    int lane = c & 31, w = c >> 5;
    float sum = x;
    #pragma unroll
    for (int o = 16; o > 0; o >>= 1) sum += __shfl_xor_sync(0xffffffffu, sum, o);
    if (lane == 0) red[w] = sum;
    __syncthreads();
    float mean = (red[0] + red[1] + red[2] + red[3]) * (1.0f / 128.0f);
    float d = x - mean;
    float sq = d * d;
    #pragma unroll
    for (int o = 16; o > 0; o >>= 1) sq += __shfl_xor_sync(0xffffffffu, sq, o);
    __syncthreads();
    if (lane == 0) red[w] = sq;
    __syncthreads();
    float var = (red[0] + red[1] + red[2] + red[3]) * (1.0f / 128.0f);
    float y = d * rsqrtf(var + 1e-5f) * g[c] + b[c];
    g_sln[n * CDIM + c] = y;
    out_s[n * CDIM + c] = y;
}

// ======================= double-buffered tf32 GEMM core =======================
// Block tile 128x128, K=128 in 8 chunks of 16, 8 warps, warp tile 32x64.

struct Task {
    const float* A; const float* Bw; const float* bias; float* C;
    int M; int Nc; int act;
};
struct Task4 { Task t[4]; };

#define GEMM_SMEM_DECL \
    __shared__ float As[2][128][20]; \
    __shared__ float Bs[2][16][136];

__device__ __forceinline__ void ldg_chunk(const float* __restrict__ A,
                                          const float* __restrict__ B,
                                          int bm, int M, int Nc, int bn, int k0, int tid,
                                          float4& a0, float4& a1, float4& b0, float4& b1) {
    int row = tid >> 2, kq = (tid & 3) << 2;
    a0 = (bm + row < M) ? *(const float4*)(A + (size_t)(bm + row) * 128 + k0 + kq)
                        : make_float4(0.f, 0.f, 0.f, 0.f);
    int row1 = row + 64;
    a1 = (bm + row1 < M) ? *(const float4*)(A + (size_t)(bm + row1) * 128 + k0 + kq)
                         : make_float4(0.f, 0.f, 0.f, 0.f);
    int kr = tid >> 5, nq = (tid & 31) << 2;
    b0 = *(const float4*)(B + (size_t)(k0 + kr) * Nc + bn + nq);
    b1 = *(const float4*)(B + (size_t)(k0 + kr + 8) * Nc + bn + nq);
}

#define STS_CHUNK(buf, a0, a1, b0, b1) do {                                   \
    int row = tid >> 2, kq = (tid & 3) << 2;                                  \
    As[buf][row][kq+0] = to_tf32(a0.x); As[buf][row][kq+1] = to_tf32(a0.y);   \
    As[buf][row][kq+2] = to_tf32(a0.z); As[buf][row][kq+3] = to_tf32(a0.w);   \
    As[buf][row+64][kq+0] = to_tf32(a1.x); As[buf][row+64][kq+1] = to_tf32(a1.y); \
    As[buf][row+64][kq+2] = to_tf32(a1.z); As[buf][row+64][kq+3] = to_tf32(a1.w); \
    int kr = tid >> 5, nq = (tid & 31) << 2;                                  \
    Bs[buf][kr][nq+0] = to_tf32(b0.x); Bs[buf][kr][nq+1] = to_tf32(b0.y);     \
    Bs[buf][kr][nq+2] = to_tf32(b0.z); Bs[buf][kr][nq+3] = to_tf32(b0.w);     \
    Bs[buf][kr+8][nq+0] = to_tf32(b1.x); Bs[buf][kr+8][nq+1] = to_tf32(b1.y); \
    Bs[buf][kr+8][nq+2] = to_tf32(b1.z); Bs[buf][kr+8][nq+3] = to_tf32(b1.w); \
} while (0)

#define MMA_CHUNK(buf) do {                                                   \
    _Pragma("unroll")                                                         \
    for (int kk = 0; kk < 16; kk += 8) {                                      \
        uint32_t bf[8][2];                                                    \
        _Pragma("unroll")                                                     \
        for (int ni = 0; ni < 8; ni++) {                                      \
            bf[ni][0] = __float_as_uint(Bs[buf][kk + tig    ][wn + ni * 8 + gid]); \
            bf[ni][1] = __float_as_uint(Bs[buf][kk + tig + 4][wn + ni * 8 + gid]); \
        }                                                                     \
        _Pragma("unroll")                                                     \
        for (int mi = 0; mi < 2; mi++) {                                      \
            uint32_t af[4];                                                   \
            af[0] = __float_as_uint(As[buf][wm + mi * 16 + gid    ][kk + tig    ]); \
            af[1] = __float_as_uint(As[buf][wm + mi * 16 + gid + 8][kk + tig    ]); \
            af[2] = __float_as_uint(As[buf][wm + mi * 16 + gid    ][kk + tig + 4]); \
            af[3] = __float_as_uint(As[buf][wm + mi * 16 + gid + 8][kk + tig + 4]); \
            _Pragma("unroll")                                                 \
            for (int ni = 0; ni < 8; ni++) mma_tf32(acc[mi][ni], af, bf[ni]); \
        }                                                                     \
    }                                                                         \
} while (0)

#define GEMM_MAINLOOP(Aptr, Bptr, Mv, Ncv)                                    \
    float acc[2][8][4];                                                       \
    _Pragma("unroll")                                                         \
    for (int mi = 0; mi < 2; mi++)                                            \
        _Pragma("unroll")                                                     \
        for (int ni = 0; ni < 8; ni++)                                        \
            _Pragma("unroll")                                                 \
            for (int t = 0; t < 4; t++) acc[mi][ni][t] = 0.0f;                \
    {                                                                         \
        float4 a0, a1, b0, b1;                                                \
        ldg_chunk(Aptr, Bptr, bm, Mv, Ncv, bn, 0, tid, a0, a1, b0, b1);       \
        STS_CHUNK(0, a0, a1, b0, b1);                                         \
        __syncthreads();                                                      \
        _Pragma("unroll")                                                     \
        for (int c = 0; c < 8; c++) {                                         \
            int cur = c & 1;                                                  \
            if (c < 7) ldg_chunk(Aptr, Bptr, bm, Mv, Ncv, bn, (c + 1) * 16, tid, a0, a1, b0, b1); \
            MMA_CHUNK(cur);                                                   \
            if (c < 7) STS_CHUNK(cur ^ 1, a0, a1, b0, b1);                    \
            __syncthreads();                                                  \
        }                                                                     \
    }

// ---------------- multi-task GEMM: C = act(A @ B + bias) ----------------
__global__ void __launch_bounds__(256)
gemm_multi(Task4 ts) {
    GEMM_SMEM_DECL
    const Task tk = ts.t[blockIdx.z];
    const int bm = blockIdx.x * 128;
    const int bn = blockIdx.y * 128;
    const int tid = threadIdx.x;
    const int warp = tid >> 5, lane = tid & 31;
    const int gid = lane >> 2, tig = lane & 3;
    const int wm = (warp & 3) * 32;
    const int wn = (warp >> 2) * 64;
    const int M = tk.M, Nc = tk.Nc;

    GEMM_MAINLOOP(tk.A, tk.Bw, M, Nc)

    #pragma unroll
    for (int mi = 0; mi < 2; mi++) {
        int r0 = bm + wm + mi * 16 + gid;
        int r1 = r0 + 8;
        #pragma unroll
        for (int ni = 0; ni < 8; ni++) {
            int col = bn + wn + ni * 8 + tig * 2;
            float bb0 = tk.bias[col], bb1 = tk.bias[col + 1];
            float v0 = acc[mi][ni][0] + bb0;
            float v1 = acc[mi][ni][1] + bb1;
            float v2 = acc[mi][ni][2] + bb0;
            float v3 = acc[mi][ni][3] + bb1;
            if (tk.act) {
                v0 = v0 / (1.0f + expf(-v0));
                v1 = v1 / (1.0f + expf(-v1));
                v2 = v2 / (1.0f + expf(-v2));
                v3 = v3 / (1.0f + expf(-v3));
            }
            if (r0 < M) { float2 o = make_float2(v0, v1); *(float2*)(tk.C + (size_t)r0 * Nc + col) = o; }
            if (r1 < M) { float2 o = make_float2(v2, v3); *(float2*)(tk.C + (size_t)r1 * Nc + col) = o; }
        }
    }
}

// ---------------- alpha[e,h] = sum_d q[dst]*k[src]*r_attn, + segment max ----------------
__global__ void alpha_kernel(const int* __restrict__ ei) {
    int warp = (blockIdx.x * blockDim.x + threadIdx.x) >> 5;
    if (warp >= N_EDGES) return;
    int lane = threadIdx.x & 31;
    int src = ei[warp];
    int dst = ei[N_EDGES + warp];
    float4 qv = *(const float4*)&g_q[(size_t)dst * CDIM + lane * 4];
    float4 kv = *(const float4*)&g_k[(size_t)src * CDIM + lane * 4];
    float4 rv = *(const float4*)&g_rattn[(size_t)warp * CDIM + lane * 4];
    float p = qv.x * kv.x * rv.x + qv.y * kv.y * rv.y + qv.z * kv.z * rv.z + qv.w * kv.w * rv.w;
    p += __shfl_xor_sync(0xffffffffu, p, 1);
    p += __shfl_xor_sync(0xffffffffu, p, 2);
    if ((lane & 3) == 0) {
        int h = lane >> 2;
        g_alpha[(size_t)warp * HEADS + h] = p;
        atomicMax(&g_m[dst * HEADS + h], enc_f(p));
    }
}

// ---------------- e = exp(alpha - m[dst]); z[dst] += e ----------------
__global__ void exp_kernel(const int* __restrict__ ei) {
    int i = blockIdx.x * blockDim.x + threadIdx.x;
    if (i >= N_EDGES * HEADS) return;
    int e = i >> 3;
    int h = i & 7;
    int dst = ei[N_EDGES + e];
    float m = dec_f(g_m[dst * HEADS + h]);
    if (!isfinite(m)) m = 0.0f;
    float ex = expf(g_alpha[i] - m);
    g_alpha[i] = ex;
    atomicAdd(&g_z[dst * HEADS + h], ex);
}

// ---------------- per-edge message + scatter-add ----------------
__global__ void msg_kernel(const int* __restrict__ ei, const float* __restrict__ dir,
                           const float* __restrict__ dij, const float* __restrict__ v,
                           float* __restrict__ out_s, float* __restrict__ out_v) {
    int e = blockIdx.x;
    int c = threadIdx.x;
    int src = ei[e];
    int dst = ei[N_EDGES + e];
    float d = dij[e];
    float cc = (d < 5.0f) ? 0.5f * (cosf(d * 0.62831853071795865f) + 1.0f) : 0.0f;

    const float* rp  = g_rproj + (size_t)e * 384;
    const float* x3s = g_x3 + (size_t)src * 384;
    const float* vs  = g_val + (size_t)src * 384;
    const float* al  = g_alpha + (size_t)e * HEADS;

    float msg[3];
    #pragma unroll
    for (int t = 0; t < 3; t++) {
        int j = c + t * 128;
        int h = j / 48;
        float a = al[h] / (g_z[dst * HEADS + h] + 1e-16f);
        msg[t] = rp[j] * x3s[j] * cc + a * vs[j];
    }

    atomicAdd(&out_s[(size_t)dst * 128 + c], msg[0]);
    float d0 = dir[e * 3 + 0], d1 = dir[e * 3 + 1], d2 = dir[e * 3 + 2];
    const float* vsrc = v + (size_t)src * 384;
    atomicAdd(&out_v[(size_t)dst * 384 + c],        d0 * msg[1] + msg[2] * vsrc[c]);
    atomicAdd(&out_v[(size_t)dst * 384 + 128 + c],  d1 * msg[1] + msg[2] * vsrc[128 + c]);
    atomicAdd(&out_v[(size_t)dst * 384 + 256 + c],  d2 * msg[1] + msg[2] * vsrc[256 + c]);
}

// ---------------- launch ----------------
extern "C" void kernel_launch(void* const* d_in, const int* in_sizes, int n_in,
                              void* d_out, int out_size) {
    const float* s   = (const float*)d_in[0];
    const float* v   = (const float*)d_in[1];
    const float* dir = (const float*)d_in[2];
    const float* dij = (const float*)d_in[3];
    const float* rij = (const float*)d_in[4];
    const int*   ei  = (const int*)d_in[5];
    const float* lng = (const float*)d_in[6];
    const float* lnb = (const float*)d_in[7];
    const float* Wq  = (const float*)d_in[8];  const float* bq  = (const float*)d_in[9];
    const float* Wk  = (const float*)d_in[10]; const float* bk  = (const float*)d_in[11];
    const float* Wg1 = (const float*)d_in[12]; const float* bg1 = (const float*)d_in[13];
    const float* Wg2 = (const float*)d_in[14]; const float* bg2 = (const float*)d_in[15];
    const float* Wv1 = (const float*)d_in[16]; const float* bv1 = (const float*)d_in[17];
    const float* Wv2 = (const float*)d_in[18]; const float* bv2 = (const float*)d_in[19];
    const float* Wre = (const float*)d_in[20]; const float* bre = (const float*)d_in[21];
    const float* Wra = (const float*)d_in[22]; const float* bra = (const float*)d_in[23];

    float* out   = (float*)d_out;
    float* out_s = out;
    float* out_v = out + (size_t)N_NODES * CDIM;
    float* out_r = out_v + (size_t)N_NODES * 3 * CDIM;

    float *p_sln, *p_q, *p_k, *p_h1, *p_h2, *p_x3, *p_val, *p_rattn, *p_rproj;
    cudaGetSymbolAddress((void**)&p_sln,   g_sln);
    cudaGetSymbolAddress((void**)&p_q,     g_q);
    cudaGetSymbolAddress((void**)&p_k,     g_k);
    cudaGetSymbolAddress((void**)&p_h1,    g_h1);
    cudaGetSymbolAddress((void**)&p_h2,    g_h2);
    cudaGetSymbolAddress((void**)&p_x3,    g_x3);
    cudaGetSymbolAddress((void**)&p_val,   g_val);
    cudaGetSymbolAddress((void**)&p_rattn, g_rattn);
    cudaGetSymbolAddress((void**)&p_rproj, g_rproj);

    cudaMemcpyAsync(out_v, v,   sizeof(float) * (size_t)N_NODES * 3 * CDIM,
                    cudaMemcpyDeviceToDevice, 0);
    cudaMemcpyAsync(out_r, rij, sizeof(float) * (size_t)N_EDGES * CDIM,
                    cudaMemcpyDeviceToDevice, 0);

    init_kernel<<<(N_NODES * HEADS + 255) / 256, 256>>>();
    ln_kernel<<<N_NODES, 128>>>(s, lng, lnb, out_s);

    const int mb_n = (N_NODES + 127) / 128;   // 157
    const int mb_e = N_EDGES / 128;           // 2500

    // 4 node GEMMs (C->C), one launch
    Task4 tA;
    tA.t[0] = { p_sln, Wq,  bq,  p_q,  N_NODES, 128, 0 };
    tA.t[1] = { p_sln, Wk,  bk,  p_k,  N_NODES, 128, 0 };
    tA.t[2] = { p_sln, Wg1, bg1, p_h1, N_NODES, 128, 1 };
    tA.t[3] = { p_sln, Wv1, bv1, p_h2, N_NODES, 128, 1 };
    gemm_multi<<<dim3(mb_n, 1, 4), 256>>>(tA);

    // 2 node GEMMs (C->3C), one launch
    Task4 tB;
    tB.t[0] = { p_h1, Wg2, bg2, p_x3,  N_NODES, 384, 0 };
    tB.t[1] = { p_h2, Wv2, bv2, p_val, N_NODES, 384, 0 };
    tB.t[2] = tB.t[0]; tB.t[3] = tB.t[0];
    gemm_multi<<<dim3(mb_n, 3, 2), 256>>>(tB);

    // edge GEMM rij @ Wre -> silu -> g_rattn (E x 128)
    Task4 tD;
    tD.t[0] = { rij, Wre, bre, p_rattn, N_EDGES, 128, 1 };
    tD.t[1] = tD.t[0]; tD.t[2] = tD.t[0]; tD.t[3] = tD.t[0];
    gemm_multi<<<dim3(mb_e, 1, 1), 256>>>(tD);

    // edge GEMM rij @ Wra (E x 384)
    Task4 tC;
    tC.t[0] = { rij, Wra, bra, p_rproj, N_EDGES, 384, 0 };
    tC.t[1] = tC.t[0]; tC.t[2] = tC.t[0]; tC.t[3] = tC.t[0];
    gemm_multi<<<dim3(mb_e, 3, 1), 256>>>(tC);

    alpha_kernel<<<N_EDGES / 8, 256>>>(ei);
    exp_kernel<<<(N_EDGES * HEADS + 255) / 256, 256>>>(ei);
    msg_kernel<<<N_EDGES, 128>>>(ei, dir, dij, v, out_s, out_v);
}

// round 5
// speedup vs baseline: 1.2841x; 1.2313x over previous
#include <cuda_runtime.h>
#include <cmath>
#include <cstdint>

#define N_NODES 20000
#define N_EDGES 320000
#define CDIM    128
#define HEADS   8

// ---------------- scratch (device globals; no allocation allowed) ----------------
__device__ __align__(16) float g_sln[N_NODES * CDIM];
__device__ __align__(16) float g_q  [N_NODES * CDIM];
__device__ __align__(16) float g_k  [N_NODES * CDIM];
__device__ __align__(16) float g_h1 [N_NODES * CDIM];
__device__ __align__(16) float g_h2 [N_NODES * CDIM];
__device__ __align__(16) float g_x3 [N_NODES * 3 * CDIM];
__device__ __align__(16) float g_val[N_NODES * 3 * CDIM];
__device__ __align__(16) float g_rattn[(size_t)N_EDGES * CDIM];
__device__ __align__(16) float g_rproj[(size_t)N_EDGES * 3 * CDIM];
__device__ __align__(16) float g_alpha[N_EDGES * HEADS];
__device__ unsigned g_m[N_NODES * HEADS];
__device__ float    g_z[N_NODES * HEADS];

__device__ __forceinline__ unsigned enc_f(float x) {
    unsigned u = __float_as_uint(x);
    return (u & 0x80000000u) ? ~u : (u | 0x80000000u);
}
__device__ __forceinline__ float dec_f(unsigned u) {
    u = (u & 0x80000000u) ? (u & 0x7fffffffu) : ~u;
    return __uint_as_float(u);
}

__device__ __forceinline__ uint32_t tf32u(float x) {
    uint32_t u;
    asm("cvt.rna.tf32.f32 %0, %1;" : "=r"(u) : "f"(x));
    return u;
}

__device__ __forceinline__ void mma_tf32(float* c, const uint32_t* a, const uint32_t* b) {
    asm volatile(
        "mma.sync.aligned.m16n8k8.row.col.f32.tf32.tf32.f32 "
        "{%0,%1,%2,%3}, {%4,%5,%6,%7}, {%8,%9}, {%0,%1,%2,%3};"
        : "+f"(c[0]), "+f"(c[1]), "+f"(c[2]), "+f"(c[3])
        : "r"(a[0]), "r"(a[1]), "r"(a[2]), "r"(a[3]), "r"(b[0]), "r"(b[1]));
}

__device__ __forceinline__ void cp16(uint32_t saddr, const void* gptr, int srcsize) {
    asm volatile("cp.async.cg.shared.global [%0], [%1], 16, %2;"
                 :: "r"(saddr), "l"(gptr), "r"(srcsize));
}
__device__ __forceinline__ void cp_commit() {
    asm volatile("cp.async.commit_group;");
}
__device__ __forceinline__ void cp_wait2() {
    asm volatile("cp.async.wait_group 2;");
}

// ---------------- init accumulators ----------------
__global__ void init_kernel() {
    int i = blockIdx.x * blockDim.x + threadIdx.x;
    if (i < N_NODES * HEADS) {
        g_m[i] = 0x007FFFFFu;  // enc(-inf)
        g_z[i] = 0.0f;
    }
}

// ---------------- layernorm ----------------
__global__ void ln_kernel(const float* __restrict__ s, const float* __restrict__ g,
                          const float* __restrict__ b, float* __restrict__ out_s) {
    int n = blockIdx.x;
    int c = threadIdx.x;
    float x = s[n * CDIM + c];
    __shared__ float red[4];
    int lane = c & 31, w = c >> 5;
    float sum = x;
    #pragma unroll
    for (int o = 16; o > 0; o >>= 1) sum += __shfl_xor_sync(0xffffffffu, sum, o);
    if (lane == 0) red[w] = sum;
    __syncthreads();
    float mean = (red[0] + red[1] + red[2] + red[3]) * (1.0f / 128.0f);
    float d = x - mean;
    float sq = d * d;
    #pragma unroll
    for (int o = 16; o > 0; o >>= 1) sq += __shfl_xor_sync(0xffffffffu, sq, o);
    __syncthreads();
    if (lane == 0) red[w] = sq;
    __syncthreads();
    float var = (red[0] + red[1] + red[2] + red[3]) * (1.0f / 128.0f);
    float y = d * rsqrtf(var + 1e-5f) * g[c] + b[c];
    g_sln[n * CDIM + c] = y;
    out_s[n * CDIM + c] = y;
}

// ============== cp.async 4-stage pipelined tf32 GEMM ==============
// Block tile 128x128, K=128 in 8 chunks of 16, 8 warps, warp tile 32x64.

struct Task {
    const float* A; const float* Bw; const float* bias; float* C;
    int M; int Nc; int act; int bn;
};
struct Task8 { Task t[8]; };

// smem (dynamic): A stages 4 x [128][20], then B stages 4 x [16][136]
#define A_STRIDE 20
#define B_STRIDE 136
#define A_STAGE  (128 * A_STRIDE)          // 2560 floats
#define B_STAGE  (16 * B_STRIDE)           // 2176 floats
#define B_BASE   (4 * A_STAGE)             // 10240 floats
#define SMEM_BYTES ((B_BASE + 4 * B_STAGE) * 4)  // 75776 bytes

__global__ void __launch_bounds__(256)
gemm_pipe(Task8 ts) {
    extern __shared__ float sm[];
    const Task tk = ts.t[blockIdx.y];
    const int bm = blockIdx.x * 128;
    const int bn = tk.bn;
    const int M = tk.M, Nc = tk.Nc;
    const float* __restrict__ A = tk.A;
    const float* __restrict__ B = tk.Bw;

    const int tid = threadIdx.x;
    const int warp = tid >> 5, lane = tid & 31;
    const int gid = lane >> 2, tig = lane & 3;
    const int wm = (warp & 3) * 32;
    const int wn = (warp >> 2) * 64;

    // per-thread copy coordinates
    const int arow = tid >> 2, akq = (tid & 3) << 2;      // A: 2 rows x 16B
    const int bkr = tid >> 5, bnq = (tid & 31) << 2;      // B: 2 krows x 16B
    const uint32_t smbase = (uint32_t)__cvta_generic_to_shared(sm);

    float acc[2][8][4];
    #pragma unroll
    for (int mi = 0; mi < 2; mi++)
        #pragma unroll
        for (int ni = 0; ni < 8; ni++)
            #pragma unroll
            for (int t = 0; t < 4; t++) acc[mi][ni][t] = 0.0f;

    // issue one stage's copies into slot st for k-offset k0
    auto issue = [&](int st, int k0) {
        int r0 = bm + arow, r1 = r0 + 64;
        const float* ga0 = A + (size_t)(r0 < M ? r0 : M - 1) * 128 + k0 + akq;
        const float* ga1 = A + (size_t)(r1 < M ? r1 : M - 1) * 128 + k0 + akq;
        cp16(smbase + (st * A_STAGE + arow * A_STRIDE + akq) * 4,        ga0, r0 < M ? 16 : 0);
        cp16(smbase + (st * A_STAGE + (arow + 64) * A_STRIDE + akq) * 4, ga1, r1 < M ? 16 : 0);
        const float* gb0 = B + (size_t)(k0 + bkr) * Nc + bn + bnq;
        const float* gb1 = B + (size_t)(k0 + bkr + 8) * Nc + bn + bnq;
        cp16(smbase + (B_BASE + st * B_STAGE + bkr * B_STRIDE + bnq) * 4,       gb0, 16);
        cp16(smbase + (B_BASE + st * B_STAGE + (bkr + 8) * B_STRIDE + bnq) * 4, gb1, 16);
    };

    issue(0, 0);  cp_commit();
    issue(1, 16); cp_commit();
    issue(2, 32); cp_commit();

    #pragma unroll
    for (int c = 0; c < 8; c++) {
        const int buf = c & 3;
        cp_wait2();
        __syncthreads();
        if (c < 5) issue((c + 3) & 3, (c + 3) * 16);
        cp_commit();

        const float* As = sm + buf * A_STAGE;
        const float* Bs = sm + B_BASE + buf * B_STAGE;
        #pragma unroll
        for (int kk = 0; kk < 16; kk += 8) {
            uint32_t bf[8][2];
            #pragma unroll
            for (int ni = 0; ni < 8; ni++) {
                bf[ni][0] = tf32u(Bs[(kk + tig    ) * B_STRIDE + wn + ni * 8 + gid]);
                bf[ni][1] = tf32u(Bs[(kk + tig + 4) * B_STRIDE + wn + ni * 8 + gid]);
            }
            #pragma unroll
            for (int mi = 0; mi < 2; mi++) {
                uint32_t af[4];
                af[0] = tf32u(As[(wm + mi * 16 + gid    ) * A_STRIDE + kk + tig    ]);
                af[1] = tf32u(As[(wm + mi * 16 + gid + 8) * A_STRIDE + kk + tig    ]);
                af[2] = tf32u(As[(wm + mi * 16 + gid    ) * A_STRIDE + kk + tig + 4]);
                af[3] = tf32u(As[(wm + mi * 16 + gid + 8) * A_STRIDE + kk + tig + 4]);
                #pragma unroll
                for (int ni = 0; ni < 8; ni++) mma_tf32(acc[mi][ni], af, bf[ni]);
            }
        }
        __syncthreads();
    }

    #pragma unroll
    for (int mi = 0; mi < 2; mi++) {
        int r0 = bm + wm + mi * 16 + gid;
        int r1 = r0 + 8;
        #pragma unroll
        for (int ni = 0; ni < 8; ni++) {
            int col = bn + wn + ni * 8 + tig * 2;
            float bb0 = tk.bias[col], bb1 = tk.bias[col + 1];
            float v0 = acc[mi][ni][0] + bb0;
            float v1 = acc[mi][ni][1] + bb1;
            float v2 = acc[mi][ni][2] + bb0;
            float v3 = acc[mi][ni][3] + bb1;
            if (tk.act) {
                v0 = v0 / (1.0f + expf(-v0));
                v1 = v1 / (1.0f + expf(-v1));
                v2 = v2 / (1.0f + expf(-v2));
                v3 = v3 / (1.0f + expf(-v3));
            }
            if (r0 < M) { float2 o = make_float2(v0, v1); *(float2*)(tk.C + (size_t)r0 * Nc + col) = o; }
            if (r1 < M) { float2 o = make_float2(v2, v3); *(float2*)(tk.C + (size_t)r1 * Nc + col) = o; }
        }
    }
}

// ---------------- alpha[e,h] = sum_d q[dst]*k[src]*r_attn, + segment max ----------------
__global__ void alpha_kernel(const int* __restrict__ ei) {
    int warp = (blockIdx.x * blockDim.x + threadIdx.x) >> 5;
    if (warp >= N_EDGES) return;
    int lane = threadIdx.x & 31;
    int src = ei[warp];
    int dst = ei[N_EDGES + warp];
    float4 qv = *(const float4*)&g_q[(size_t)dst * CDIM + lane * 4];
    float4 kv = *(const float4*)&g_k[(size_t)src * CDIM + lane * 4];
    float4 rv = *(const float4*)&g_rattn[(size_t)warp * CDIM + lane * 4];
    float p = qv.x * kv.x * rv.x + qv.y * kv.y * rv.y + qv.z * kv.z * rv.z + qv.w * kv.w * rv.w;
    p += __shfl_xor_sync(0xffffffffu, p, 1);
    p += __shfl_xor_sync(0xffffffffu, p, 2);
    if ((lane & 3) == 0) {
        int h = lane >> 2;
        g_alpha[(size_t)warp * HEADS + h] = p;
        atomicMax(&g_m[dst * HEADS + h], enc_f(p));
    }
}

// ---------------- e = exp(alpha - m[dst]); z[dst] += e ----------------
__global__ void exp_kernel(const int* __restrict__ ei) {
    int i = blockIdx.x * blockDim.x + threadIdx.x;
    if (i >= N_EDGES * HEADS) return;
    int e = i >> 3;
    int h = i & 7;
    int dst = ei[N_EDGES + e];
    float m = dec_f(g_m[dst * HEADS + h]);
    if (!isfinite(m)) m = 0.0f;
    float ex = expf(g_alpha[i] - m);
    g_alpha[i] = ex;
    atomicAdd(&g_z[dst * HEADS + h], ex);
}

// ---------------- per-edge message + scatter-add ----------------
__global__ void msg_kernel(const int* __restrict__ ei, const float* __restrict__ dir,
                           const float* __restrict__ dij, const float* __restrict__ v,
                           float* __restrict__ out_s, float* __restrict__ out_v) {
    int e = blockIdx.x;
    int c = threadIdx.x;
    int src = ei[e];
    int dst = ei[N_EDGES + e];
    float d = dij[e];
    float cc = (d < 5.0f) ? 0.5f * (cosf(d * 0.62831853071795865f) + 1.0f) : 0.0f;

    const float* rp  = g_rproj + (size_t)e * 384;
    const float* x3s = g_x3 + (size_t)src * 384;
    const float* vs  = g_val + (size_t)src * 384;
    const float* al  = g_alpha + (size_t)e * HEADS;

    float msg[3];
    #pragma unroll
    for (int t = 0; t < 3; t++) {
        int j = c + t * 128;
        int h = j / 48;
        float a = al[h] / (g_z[dst * HEADS + h] + 1e-16f);
        msg[t] = rp[j] * x3s[j] * cc + a * vs[j];
    }

    atomicAdd(&out_s[(size_t)dst * 128 + c], msg[0]);
    float d0 = dir[e * 3 + 0], d1 = dir[e * 3 + 1], d2 = dir[e * 3 + 2];
    const float* vsrc = v + (size_t)src * 384;
    atomicAdd(&out_v[(size_t)dst * 384 + c],        d0 * msg[1] + msg[2] * vsrc[c]);
    atomicAdd(&out_v[(size_t)dst * 384 + 128 + c],  d1 * msg[1] + msg[2] * vsrc[128 + c]);
    atomicAdd(&out_v[(size_t)dst * 384 + 256 + c],  d2 * msg[1] + msg[2] * vsrc[256 + c]);
}

// ---------------- launch ----------------
extern "C" void kernel_launch(void* const* d_in, const int* in_sizes, int n_in,
                              void* d_out, int out_size) {
    const float* s   = (const float*)d_in[0];
    const float* v   = (const float*)d_in[1];
    const float* dir = (const float*)d_in[2];
    const float* dij = (const float*)d_in[3];
    const float* rij = (const float*)d_in[4];
    const int*   ei  = (const int*)d_in[5];
    const float* lng = (const float*)d_in[6];
    const float* lnb = (const float*)d_in[7];
    const float* Wq  = (const float*)d_in[8];  const float* bq  = (const float*)d_in[9];
    const float* Wk  = (const float*)d_in[10]; const float* bk  = (const float*)d_in[11];
    const float* Wg1 = (const float*)d_in[12]; const float* bg1 = (const float*)d_in[13];
    const float* Wg2 = (const float*)d_in[14]; const float* bg2 = (const float*)d_in[15];
    const float* Wv1 = (const float*)d_in[16]; const float* bv1 = (const float*)d_in[17];
    const float* Wv2 = (const float*)d_in[18]; const float* bv2 = (const float*)d_in[19];
    const float* Wre = (const float*)d_in[20]; const float* bre = (const float*)d_in[21];
    const float* Wra = (const float*)d_in[22]; const float* bra = (const float*)d_in[23];

    float* out   = (float*)d_out;
    float* out_s = out;
    float* out_v = out + (size_t)N_NODES * CDIM;
    float* out_r = out_v + (size_t)N_NODES * 3 * CDIM;

    float *p_sln, *p_q, *p_k, *p_h1, *p_h2, *p_x3, *p_val, *p_rattn, *p_rproj;
    cudaGetSymbolAddress((void**)&p_sln,   g_sln);
    cudaGetSymbolAddress((void**)&p_q,     g_q);
    cudaGetSymbolAddress((void**)&p_k,     g_k);
    cudaGetSymbolAddress((void**)&p_h1,    g_h1);
    cudaGetSymbolAddress((void**)&p_h2,    g_h2);
    cudaGetSymbolAddress((void**)&p_x3,    g_x3);
    cudaGetSymbolAddress((void**)&p_val,   g_val);
    cudaGetSymbolAddress((void**)&p_rattn, g_rattn);
    cudaGetSymbolAddress((void**)&p_rproj, g_rproj);

    cudaFuncSetAttribute(gemm_pipe, cudaFuncAttributeMaxDynamicSharedMemorySize, SMEM_BYTES);

    cudaMemcpyAsync(out_v, v,   sizeof(float) * (size_t)N_NODES * 3 * CDIM,
                    cudaMemcpyDeviceToDevice, 0);
    cudaMemcpyAsync(out_r, rij, sizeof(float) * (size_t)N_EDGES * CDIM,
                    cudaMemcpyDeviceToDevice, 0);

    init_kernel<<<(N_NODES * HEADS + 255) / 256, 256>>>();
    ln_kernel<<<N_NODES, 128>>>(s, lng, lnb, out_s);

    const int mb_n = (N_NODES + 127) / 128;   // 157
    const int mb_e = N_EDGES / 128;           // 2500

    // 4 node GEMMs (C->C), one launch, task = blockIdx.y
    Task8 tA;
    tA.t[0] = { p_sln, Wq,  bq,  p_q,  N_NODES, 128, 0, 0 };
    tA.t[1] = { p_sln, Wk,  bk,  p_k,  N_NODES, 128, 0, 0 };
    tA.t[2] = { p_sln, Wg1, bg1, p_h1, N_NODES, 128, 1, 0 };
    tA.t[3] = { p_sln, Wv1, bv1, p_h2, N_NODES, 128, 1, 0 };
    tA.t[4] = tA.t[0]; tA.t[5] = tA.t[0]; tA.t[6] = tA.t[0]; tA.t[7] = tA.t[0];
    gemm_pipe<<<dim3(mb_n, 4), 256, SMEM_BYTES>>>(tA);

    // 2 node GEMMs (C->3C) x 3 column tiles, one launch
    Task8 tB;
    tB.t[0] = { p_h1, Wg2, bg2, p_x3,  N_NODES, 384, 0, 0   };
    tB.t[1] = { p_h1, Wg2, bg2, p_x3,  N_NODES, 384, 0, 128 };
    tB.t[2] = { p_h1, Wg2, bg2, p_x3,  N_NODES, 384, 0, 256 };
    tB.t[3] = { p_h2, Wv2, bv2, p_val, N_NODES, 384, 0, 0   };
    tB.t[4] = { p_h2, Wv2, bv2, p_val, N_NODES, 384, 0, 128 };
    tB.t[5] = { p_h2, Wv2, bv2, p_val, N_NODES, 384, 0, 256 };
    tB.t[6] = tB.t[0]; tB.t[7] = tB.t[0];
    gemm_pipe<<<dim3(mb_n, 6), 256, SMEM_BYTES>>>(tB);

    // edge GEMMs: Wra (3 column tiles) + Wre (silu), one launch
    Task8 tE;
    tE.t[0] = { rij, Wra, bra, p_rproj, N_EDGES, 384, 0, 0   };
    tE.t[1] = { rij, Wra, bra, p_rproj, N_EDGES, 384, 0, 128 };
    tE.t[2] = { rij, Wra, bra, p_rproj, N_EDGES, 384, 0, 256 };
    tE.t[3] = { rij, Wre, bre, p_rattn, N_EDGES, 128, 1, 0   };
    tE.t[4] = tE.t[0]; tE.t[5] = tE.t[0]; tE.t[6] = tE.t[0]; tE.t[7] = tE.t[0];
    gemm_pipe<<<dim3(mb_e, 4), 256, SMEM_BYTES>>>(tE);

    alpha_kernel<<<N_EDGES / 8, 256>>>(ei);
    exp_kernel<<<(N_EDGES * HEADS + 255) / 256, 256>>>(ei);
    msg_kernel<<<N_EDGES, 128>>>(ei, dir, dij, v, out_s, out_v);
}